// round 10
// baseline (speedup 1.0000x reference)
#include <cuda_runtime.h>
#include <math.h>
#include <stdint.h>

// Problem constants
#define NTOK 2048
#define DIM  1024
#define FF   4096
#define FSH  2048
#define NE   8
#define TOPK 2
#define NSLOT (NTOK*TOPK)

// Tiling: BM=128, BN=64, BK=16, double-buffered cp.async (R4 config — best)
#define BM 128
#define BN 64
#define BK 16
#define PA 20
#define PB 72

// ---- scratch ----
__device__ float g_act[(size_t)NSLOT * FF];
__device__ float g_eo[(size_t)NSLOT * DIM];
__device__ float g_hs[(size_t)NTOK * FSH];
__device__ float g_topw[NTOK * TOPK];
__device__ int   g_topi[NTOK * TOPK];
__device__ int   g_slot_tok[NSLOT];
__device__ float g_slot_w[NSLOT];
__device__ int   g_slot_dst[NSLOT];
__device__ int   g_cnt[NE];
__device__ int   g_off[NE + 1];

// ---------------------------------------------------------------------------
__device__ __forceinline__ uint32_t f2tf32(float x) {
    uint32_t r;
    asm("cvt.rna.tf32.f32 %0, %1;" : "=r"(r) : "f"(x));
    return r;
}

__device__ __forceinline__ void mma_tf32(float& c0, float& c1, float& c2, float& c3,
                                         uint32_t a0, uint32_t a1, uint32_t a2, uint32_t a3,
                                         uint32_t b0, uint32_t b1)
{
    asm volatile(
        "mma.sync.aligned.m16n8k8.row.col.f32.tf32.tf32.f32 "
        "{%0,%1,%2,%3},{%4,%5,%6,%7},{%8,%9},{%0,%1,%2,%3};"
        : "+f"(c0), "+f"(c1), "+f"(c2), "+f"(c3)
        : "r"(a0), "r"(a1), "r"(a2), "r"(a3), "r"(b0), "r"(b1));
}

__device__ __forceinline__ void cp16(uint32_t dst_smem, const float* src) {
    asm volatile("cp.async.cg.shared.global [%0], [%1], 16;"
                 :: "r"(dst_smem), "l"(src));
}
#define CP_COMMIT() asm volatile("cp.async.commit_group;")
#define CP_WAIT1()  asm volatile("cp.async.wait_group 1;" ::: "memory")

// ---------------------------------------------------------------------------
// Router: logits + softmax + top-2 per token. No global counting here.
// ---------------------------------------------------------------------------
__global__ void router_kernel(const float* __restrict__ x,
                              const float* __restrict__ gate_w)
{
    const int n = blockIdx.x;
    const int tid = threadIdx.x;
    __shared__ float sred[NE][128];

    float acc[NE];
#pragma unroll
    for (int e = 0; e < NE; e++) acc[e] = 0.f;

    const float* xr = x + (size_t)n * DIM;
    for (int d = tid; d < DIM; d += 128) {
        float xv = xr[d];
#pragma unroll
        for (int e = 0; e < NE; e++)
            acc[e] = fmaf(xv, gate_w[e * DIM + d], acc[e]);
    }
#pragma unroll
    for (int e = 0; e < NE; e++) sred[e][tid] = acc[e];
    __syncthreads();

    if (tid < NE) {
        float s = 0.f;
        for (int i = 0; i < 128; i++) s += sred[tid][i];
        sred[tid][0] = s;
    }
    __syncthreads();

    if (tid == 0) {
        float lg[NE];
#pragma unroll
        for (int e = 0; e < NE; e++) lg[e] = sred[e][0];
        float mx = lg[0];
#pragma unroll
        for (int e = 1; e < NE; e++) mx = fmaxf(mx, lg[e]);
        float se = 0.f, p[NE];
#pragma unroll
        for (int e = 0; e < NE; e++) { p[e] = expf(lg[e] - mx); se += p[e]; }
        float inv = 1.f / se;
#pragma unroll
        for (int e = 0; e < NE; e++) p[e] *= inv;

        int i1 = 0; float v1 = p[0];
#pragma unroll
        for (int e = 1; e < NE; e++) if (p[e] > v1) { v1 = p[e]; i1 = e; }
        int i2 = -1; float v2 = -1.f;
#pragma unroll
        for (int e = 0; e < NE; e++) if (e != i1 && p[e] > v2) { v2 = p[e]; i2 = e; }

        g_topi[n * 2 + 0] = i1;  g_topw[n * 2 + 0] = v1;
        g_topi[n * 2 + 1] = i2;  g_topw[n * 2 + 1] = v2;
    }
}

// ---------------------------------------------------------------------------
// Scan+fill in ONE single-block kernel: count g_topi occurrences, exclusive
// scan, then compact token assignments into per-expert slot ranges.
// ---------------------------------------------------------------------------
__global__ void scanfill_kernel()
{
    __shared__ int sm_cnt[NE];
    __shared__ int sm_off[NE];
    __shared__ int sm_cur[NE];
    const int t = threadIdx.x;

    if (t < NE) sm_cnt[t] = 0;
    __syncthreads();

    for (int i = t; i < NSLOT; i += 256)
        atomicAdd(&sm_cnt[g_topi[i]], 1);
    __syncthreads();

    if (t == 0) {
        int r = 0;
        for (int e = 0; e < NE; e++) {
            sm_off[e] = r;
            sm_cur[e] = 0;
            r += sm_cnt[e];
        }
        g_off[NE] = r;
    }
    __syncthreads();
    if (t < NE) {
        g_cnt[t] = sm_cnt[t];
        g_off[t] = sm_off[t];
    }
    __syncthreads();

    for (int i = t; i < NSLOT; i += 256) {
        int e = g_topi[i];
        int pos = atomicAdd(&sm_cur[e], 1);
        int slot = sm_off[e] + pos;
        g_slot_tok[slot] = i >> 1;
        g_slot_w[slot]   = g_topw[i];
        g_slot_dst[slot] = i;
    }
}

// ---------------------------------------------------------------------------
// Routed gate+up GEMM (cp.async double-buffered) + SwiGLU + weight  [R4]
// ---------------------------------------------------------------------------
__global__ __launch_bounds__(256)
void gemm_gateup_routed(const float* __restrict__ x,
                        const float* __restrict__ gate_k,
                        const float* __restrict__ up_k)
{
    const int e = blockIdx.z;
    const int cnt = g_cnt[e];
    const int rowbase = blockIdx.y * BM;
    if (rowbase >= cnt) return;
    const int off = g_off[e];
    const int n0 = blockIdx.x * BN;
    const float* __restrict__ Bg = gate_k + (size_t)e * DIM * FF;
    const float* __restrict__ Bu = up_k   + (size_t)e * DIM * FF;

    __shared__ float Am[2][BM * PA];
    __shared__ float Bgs[2][BK * PB];
    __shared__ float Bus[2][BK * PB];

    const int t = threadIdx.x;
    const int wid = t >> 5, lane = t & 31;
    const int q = lane >> 2, r = lane & 3;
    const int wm = (wid >> 1) * 32;
    const int wn = (wid & 1) * 32;

    const int a_row = t >> 1, a_seg = (t & 1) * 8;
    int m_g = rowbase + a_row;
    if (m_g >= cnt) m_g = cnt - 1;
    const float* a_src = x + (size_t)g_slot_tok[off + m_g] * DIM + a_seg;

    const int b_row = t >> 4, b_col = (t & 15) * 4;
    const float* bg_src = Bg + (size_t)b_row * FF + n0 + b_col;
    const float* bu_src = Bu + (size_t)b_row * FF + n0 + b_col;

    const uint32_t sAm = (uint32_t)__cvta_generic_to_shared(&Am[0][0]);
    const uint32_t sBg = (uint32_t)__cvta_generic_to_shared(&Bgs[0][0]);
    const uint32_t sBu = (uint32_t)__cvta_generic_to_shared(&Bus[0][0]);
    const uint32_t aoff = (a_row * PA + a_seg) * 4;
    const uint32_t boff = (b_row * PB + b_col) * 4;
    const uint32_t szA = BM * PA * 4, szB = BK * PB * 4;

    float accg[2][4][4], accu[2][4][4];
#pragma unroll
    for (int i = 0; i < 2; i++)
#pragma unroll
        for (int j = 0; j < 4; j++)
#pragma unroll
            for (int c = 0; c < 4; c++) { accg[i][j][c] = 0.f; accu[i][j][c] = 0.f; }

    cp16(sAm + aoff,      a_src);
    cp16(sAm + aoff + 16, a_src + 4);
    cp16(sBg + boff, bg_src);
    cp16(sBu + boff, bu_src);
    CP_COMMIT();

#pragma unroll 1
    for (int k0 = 0; k0 < DIM; k0 += BK) {
        const int cur = (k0 >> 4) & 1;
        if (k0 + BK < DIM) {
            const uint32_t nb = (cur ^ 1);
            cp16(sAm + nb * szA + aoff,      a_src + k0 + BK);
            cp16(sAm + nb * szA + aoff + 16, a_src + k0 + BK + 4);
            cp16(sBg + nb * szB + boff, bg_src + (size_t)(k0 + BK) * FF);
            cp16(sBu + nb * szB + boff, bu_src + (size_t)(k0 + BK) * FF);
        }
        CP_COMMIT();
        CP_WAIT1();
        __syncthreads();

        const float* A_  = Am[cur];
        const float* BG_ = Bgs[cur];
        const float* BU_ = Bus[cur];
#pragma unroll
        for (int ks = 0; ks < 2; ks++) {
            const int kb = ks * 8;
            uint32_t af[2][4];
#pragma unroll
            for (int mt = 0; mt < 2; mt++) {
                int mr = wm + mt * 16 + q;
                af[mt][0] = f2tf32(A_[mr * PA + kb + r]);
                af[mt][1] = f2tf32(A_[(mr + 8) * PA + kb + r]);
                af[mt][2] = f2tf32(A_[mr * PA + kb + 4 + r]);
                af[mt][3] = f2tf32(A_[(mr + 8) * PA + kb + 4 + r]);
            }
            uint32_t bgf[4][2], buf[4][2];
#pragma unroll
            for (int nt = 0; nt < 4; nt++) {
                int nc = wn + nt * 8 + q;
                bgf[nt][0] = f2tf32(BG_[(kb + r) * PB + nc]);
                bgf[nt][1] = f2tf32(BG_[(kb + 4 + r) * PB + nc]);
                buf[nt][0] = f2tf32(BU_[(kb + r) * PB + nc]);
                buf[nt][1] = f2tf32(BU_[(kb + 4 + r) * PB + nc]);
            }
#pragma unroll
            for (int mt = 0; mt < 2; mt++)
#pragma unroll
                for (int nt = 0; nt < 4; nt++) {
                    mma_tf32(accg[mt][nt][0], accg[mt][nt][1], accg[mt][nt][2], accg[mt][nt][3],
                             af[mt][0], af[mt][1], af[mt][2], af[mt][3], bgf[nt][0], bgf[nt][1]);
                    mma_tf32(accu[mt][nt][0], accu[mt][nt][1], accu[mt][nt][2], accu[mt][nt][3],
                             af[mt][0], af[mt][1], af[mt][2], af[mt][3], buf[nt][0], buf[nt][1]);
                }
        }
        __syncthreads();
    }

#pragma unroll
    for (int mt = 0; mt < 2; mt++) {
        int r0 = wm + mt * 16 + q;
#pragma unroll
        for (int half = 0; half < 2; half++) {
            int m = rowbase + r0 + half * 8;
            if (m < cnt) {
                int slot = off + m;
                float w = g_slot_w[slot];
                float* dst = g_act + (size_t)slot * FF + n0;
#pragma unroll
                for (int nt = 0; nt < 4; nt++) {
                    int cb = wn + nt * 8 + 2 * r;
                    float gv0 = accg[mt][nt][half * 2 + 0];
                    float gv1 = accg[mt][nt][half * 2 + 1];
                    float uv0 = accu[mt][nt][half * 2 + 0];
                    float uv1 = accu[mt][nt][half * 2 + 1];
                    dst[cb]     = w * (gv0 / (1.f + expf(-gv0))) * uv0;
                    dst[cb + 1] = w * (gv1 / (1.f + expf(-gv1))) * uv1;
                }
            }
        }
    }
}

// ---------------------------------------------------------------------------
// Routed down GEMM (cp.async double-buffered)  [R4]
// ---------------------------------------------------------------------------
__global__ __launch_bounds__(256)
void gemm_down_routed(const float* __restrict__ down_k)
{
    const int e = blockIdx.z;
    const int cnt = g_cnt[e];
    const int rowbase = blockIdx.y * BM;
    if (rowbase >= cnt) return;
    const int off = g_off[e];
    const int n0 = blockIdx.x * BN;
    const float* __restrict__ B = down_k + (size_t)e * FF * DIM;

    __shared__ float Am[2][BM * PA];
    __shared__ float Bs[2][BK * PB];

    const int t = threadIdx.x;
    const int wid = t >> 5, lane = t & 31;
    const int q = lane >> 2, r = lane & 3;
    const int wm = (wid >> 1) * 32;
    const int wn = (wid & 1) * 32;

    const int a_row = t >> 1, a_seg = (t & 1) * 8;
    int m_g = rowbase + a_row;
    if (m_g >= cnt) m_g = cnt - 1;
    const float* a_src = g_act + (size_t)(off + m_g) * FF + a_seg;

    const int b_row = t >> 4, b_col = (t & 15) * 4;
    const float* b_src = B + (size_t)b_row * DIM + n0 + b_col;

    const uint32_t sAm = (uint32_t)__cvta_generic_to_shared(&Am[0][0]);
    const uint32_t sBs = (uint32_t)__cvta_generic_to_shared(&Bs[0][0]);
    const uint32_t aoff = (a_row * PA + a_seg) * 4;
    const uint32_t boff = (b_row * PB + b_col) * 4;
    const uint32_t szA = BM * PA * 4, szB = BK * PB * 4;

    float acc[2][4][4];
#pragma unroll
    for (int i = 0; i < 2; i++)
#pragma unroll
        for (int j = 0; j < 4; j++)
#pragma unroll
            for (int c = 0; c < 4; c++) acc[i][j][c] = 0.f;

    cp16(sAm + aoff,      a_src);
    cp16(sAm + aoff + 16, a_src + 4);
    cp16(sBs + boff, b_src);
    CP_COMMIT();

#pragma unroll 1
    for (int k0 = 0; k0 < FF; k0 += BK) {
        const int cur = (k0 >> 4) & 1;
        if (k0 + BK < FF) {
            const uint32_t nb = (cur ^ 1);
            cp16(sAm + nb * szA + aoff,      a_src + k0 + BK);
            cp16(sAm + nb * szA + aoff + 16, a_src + k0 + BK + 4);
            cp16(sBs + nb * szB + boff, b_src + (size_t)(k0 + BK) * DIM);
        }
        CP_COMMIT();
        CP_WAIT1();
        __syncthreads();

        const float* A_ = Am[cur];
        const float* B_ = Bs[cur];
#pragma unroll
        for (int ks = 0; ks < 2; ks++) {
            const int kb = ks * 8;
            uint32_t af[2][4];
#pragma unroll
            for (int mt = 0; mt < 2; mt++) {
                int mr = wm + mt * 16 + q;
                af[mt][0] = f2tf32(A_[mr * PA + kb + r]);
                af[mt][1] = f2tf32(A_[(mr + 8) * PA + kb + r]);
                af[mt][2] = f2tf32(A_[mr * PA + kb + 4 + r]);
                af[mt][3] = f2tf32(A_[(mr + 8) * PA + kb + 4 + r]);
            }
            uint32_t bf[4][2];
#pragma unroll
            for (int nt = 0; nt < 4; nt++) {
                int nc = wn + nt * 8 + q;
                bf[nt][0] = f2tf32(B_[(kb + r) * PB + nc]);
                bf[nt][1] = f2tf32(B_[(kb + 4 + r) * PB + nc]);
            }
#pragma unroll
            for (int mt = 0; mt < 2; mt++)
#pragma unroll
                for (int nt = 0; nt < 4; nt++)
                    mma_tf32(acc[mt][nt][0], acc[mt][nt][1], acc[mt][nt][2], acc[mt][nt][3],
                             af[mt][0], af[mt][1], af[mt][2], af[mt][3], bf[nt][0], bf[nt][1]);
        }
        __syncthreads();
    }

#pragma unroll
    for (int mt = 0; mt < 2; mt++) {
        int r0 = wm + mt * 16 + q;
#pragma unroll
        for (int half = 0; half < 2; half++) {
            int m = rowbase + r0 + half * 8;
            if (m < cnt) {
                int dst_row = g_slot_dst[off + m];
                float* dst = g_eo + (size_t)dst_row * DIM + n0;
#pragma unroll
                for (int nt = 0; nt < 4; nt++) {
                    int cb = wn + nt * 8 + 2 * r;
                    dst[cb]     = acc[mt][nt][half * 2 + 0];
                    dst[cb + 1] = acc[mt][nt][half * 2 + 1];
                }
            }
        }
    }
}

// ---------------------------------------------------------------------------
// Shared expert gate+up + SwiGLU (cp.async double-buffered)  [R4]
// ---------------------------------------------------------------------------
__global__ __launch_bounds__(256)
void gemm_gateup_shared(const float* __restrict__ x,
                        const float* __restrict__ sh_gate,
                        const float* __restrict__ sh_up)
{
    const int rowbase = blockIdx.y * BM;
    const int n0 = blockIdx.x * BN;

    __shared__ float Am[2][BM * PA];
    __shared__ float Bgs[2][BK * PB];
    __shared__ float Bus[2][BK * PB];

    const int t = threadIdx.x;
    const int wid = t >> 5, lane = t & 31;
    const int q = lane >> 2, r = lane & 3;
    const int wm = (wid >> 1) * 32;
    const int wn = (wid & 1) * 32;

    const int a_row = t >> 1, a_seg = (t & 1) * 8;
    const float* a_src = x + (size_t)(rowbase + a_row) * DIM + a_seg;

    const int b_row = t >> 4, b_col = (t & 15) * 4;
    const float* bg_src = sh_gate + (size_t)b_row * FSH + n0 + b_col;
    const float* bu_src = sh_up   + (size_t)b_row * FSH + n0 + b_col;

    const uint32_t sAm = (uint32_t)__cvta_generic_to_shared(&Am[0][0]);
    const uint32_t sBg = (uint32_t)__cvta_generic_to_shared(&Bgs[0][0]);
    const uint32_t sBu = (uint32_t)__cvta_generic_to_shared(&Bus[0][0]);
    const uint32_t aoff = (a_row * PA + a_seg) * 4;
    const uint32_t boff = (b_row * PB + b_col) * 4;
    const uint32_t szA = BM * PA * 4, szB = BK * PB * 4;

    float accg[2][4][4], accu[2][4][4];
#pragma unroll
    for (int i = 0; i < 2; i++)
#pragma unroll
        for (int j = 0; j < 4; j++)
#pragma unroll
            for (int c = 0; c < 4; c++) { accg[i][j][c] = 0.f; accu[i][j][c] = 0.f; }

    cp16(sAm + aoff,      a_src);
    cp16(sAm + aoff + 16, a_src + 4);
    cp16(sBg + boff, bg_src);
    cp16(sBu + boff, bu_src);
    CP_COMMIT();

#pragma unroll 1
    for (int k0 = 0; k0 < DIM; k0 += BK) {
        const int cur = (k0 >> 4) & 1;
        if (k0 + BK < DIM) {
            const uint32_t nb = (cur ^ 1);
            cp16(sAm + nb * szA + aoff,      a_src + k0 + BK);
            cp16(sAm + nb * szA + aoff + 16, a_src + k0 + BK + 4);
            cp16(sBg + nb * szB + boff, bg_src + (size_t)(k0 + BK) * FSH);
            cp16(sBu + nb * szB + boff, bu_src + (size_t)(k0 + BK) * FSH);
        }
        CP_COMMIT();
        CP_WAIT1();
        __syncthreads();

        const float* A_  = Am[cur];
        const float* BG_ = Bgs[cur];
        const float* BU_ = Bus[cur];
#pragma unroll
        for (int ks = 0; ks < 2; ks++) {
            const int kb = ks * 8;
            uint32_t af[2][4];
#pragma unroll
            for (int mt = 0; mt < 2; mt++) {
                int mr = wm + mt * 16 + q;
                af[mt][0] = f2tf32(A_[mr * PA + kb + r]);
                af[mt][1] = f2tf32(A_[(mr + 8) * PA + kb + r]);
                af[mt][2] = f2tf32(A_[mr * PA + kb + 4 + r]);
                af[mt][3] = f2tf32(A_[(mr + 8) * PA + kb + 4 + r]);
            }
            uint32_t bgf[4][2], buf[4][2];
#pragma unroll
            for (int nt = 0; nt < 4; nt++) {
                int nc = wn + nt * 8 + q;
                bgf[nt][0] = f2tf32(BG_[(kb + r) * PB + nc]);
                bgf[nt][1] = f2tf32(BG_[(kb + 4 + r) * PB + nc]);
                buf[nt][0] = f2tf32(BU_[(kb + r) * PB + nc]);
                buf[nt][1] = f2tf32(BU_[(kb + 4 + r) * PB + nc]);
            }
#pragma unroll
            for (int mt = 0; mt < 2; mt++)
#pragma unroll
                for (int nt = 0; nt < 4; nt++) {
                    mma_tf32(accg[mt][nt][0], accg[mt][nt][1], accg[mt][nt][2], accg[mt][nt][3],
                             af[mt][0], af[mt][1], af[mt][2], af[mt][3], bgf[nt][0], bgf[nt][1]);
                    mma_tf32(accu[mt][nt][0], accu[mt][nt][1], accu[mt][nt][2], accu[mt][nt][3],
                             af[mt][0], af[mt][1], af[mt][2], af[mt][3], buf[nt][0], buf[nt][1]);
                }
        }
        __syncthreads();
    }

#pragma unroll
    for (int mt = 0; mt < 2; mt++) {
        int r0 = wm + mt * 16 + q;
#pragma unroll
        for (int half = 0; half < 2; half++) {
            int m = rowbase + r0 + half * 8;
            float* dst = g_hs + (size_t)m * FSH + n0;
#pragma unroll
            for (int nt = 0; nt < 4; nt++) {
                int cb = wn + nt * 8 + 2 * r;
                float gv0 = accg[mt][nt][half * 2 + 0];
                float gv1 = accg[mt][nt][half * 2 + 1];
                float uv0 = accu[mt][nt][half * 2 + 0];
                float uv1 = accu[mt][nt][half * 2 + 1];
                dst[cb]     = (gv0 / (1.f + expf(-gv0))) * uv0;
                dst[cb + 1] = (gv1 / (1.f + expf(-gv1))) * uv1;
            }
        }
    }
}

// ---------------------------------------------------------------------------
// Shared down GEMM + final combine (cp.async double-buffered)  [R4]
// ---------------------------------------------------------------------------
__global__ __launch_bounds__(256)
void gemm_down_shared(const float* __restrict__ sh_down,
                      float* __restrict__ out)
{
    const int rowbase = blockIdx.y * BM;
    const int n0 = blockIdx.x * BN;

    __shared__ float Am[2][BM * PA];
    __shared__ float Bs[2][BK * PB];

    const int t = threadIdx.x;
    const int wid = t >> 5, lane = t & 31;
    const int q = lane >> 2, r = lane & 3;
    const int wm = (wid >> 1) * 32;
    const int wn = (wid & 1) * 32;

    const int a_row = t >> 1, a_seg = (t & 1) * 8;
    const float* a_src = g_hs + (size_t)(rowbase + a_row) * FSH + a_seg;

    const int b_row = t >> 4, b_col = (t & 15) * 4;
    const float* b_src = sh_down + (size_t)b_row * DIM + n0 + b_col;

    const uint32_t sAm = (uint32_t)__cvta_generic_to_shared(&Am[0][0]);
    const uint32_t sBs = (uint32_t)__cvta_generic_to_shared(&Bs[0][0]);
    const uint32_t aoff = (a_row * PA + a_seg) * 4;
    const uint32_t boff = (b_row * PB + b_col) * 4;
    const uint32_t szA = BM * PA * 4, szB = BK * PB * 4;

    float acc[2][4][4];
#pragma unroll
    for (int i = 0; i < 2; i++)
#pragma unroll
        for (int j = 0; j < 4; j++)
#pragma unroll
            for (int c = 0; c < 4; c++) acc[i][j][c] = 0.f;

    cp16(sAm + aoff,      a_src);
    cp16(sAm + aoff + 16, a_src + 4);
    cp16(sBs + boff, b_src);
    CP_COMMIT();

#pragma unroll 1
    for (int k0 = 0; k0 < FSH; k0 += BK) {
        const int cur = (k0 >> 4) & 1;
        if (k0 + BK < FSH) {
            const uint32_t nb = (cur ^ 1);
            cp16(sAm + nb * szA + aoff,      a_src + k0 + BK);
            cp16(sAm + nb * szA + aoff + 16, a_src + k0 + BK + 4);
            cp16(sBs + nb * szB + boff, b_src + (size_t)(k0 + BK) * DIM);
        }
        CP_COMMIT();
        CP_WAIT1();
        __syncthreads();

        const float* A_ = Am[cur];
        const float* B_ = Bs[cur];
#pragma unroll
        for (int ks = 0; ks < 2; ks++) {
            const int kb = ks * 8;
            uint32_t af[2][4];
#pragma unroll
            for (int mt = 0; mt < 2; mt++) {
                int mr = wm + mt * 16 + q;
                af[mt][0] = f2tf32(A_[mr * PA + kb + r]);
                af[mt][1] = f2tf32(A_[(mr + 8) * PA + kb + r]);
                af[mt][2] = f2tf32(A_[mr * PA + kb + 4 + r]);
                af[mt][3] = f2tf32(A_[(mr + 8) * PA + kb + 4 + r]);
            }
            uint32_t bf[4][2];
#pragma unroll
            for (int nt = 0; nt < 4; nt++) {
                int nc = wn + nt * 8 + q;
                bf[nt][0] = f2tf32(B_[(kb + r) * PB + nc]);
                bf[nt][1] = f2tf32(B_[(kb + 4 + r) * PB + nc]);
            }
#pragma unroll
            for (int mt = 0; mt < 2; mt++)
#pragma unroll
                for (int nt = 0; nt < 4; nt++)
                    mma_tf32(acc[mt][nt][0], acc[mt][nt][1], acc[mt][nt][2], acc[mt][nt][3],
                             af[mt][0], af[mt][1], af[mt][2], af[mt][3], bf[nt][0], bf[nt][1]);
        }
        __syncthreads();
    }

#pragma unroll
    for (int mt = 0; mt < 2; mt++) {
        int r0 = wm + mt * 16 + q;
#pragma unroll
        for (int half = 0; half < 2; half++) {
            int m = rowbase + r0 + half * 8;
            const float* eo0 = g_eo + (size_t)(m * 2)     * DIM + n0;
            const float* eo1 = g_eo + (size_t)(m * 2 + 1) * DIM + n0;
            float* dst = out + (size_t)m * DIM + n0;
#pragma unroll
            for (int nt = 0; nt < 4; nt++) {
                int cb = wn + nt * 8 + 2 * r;
                dst[cb]     = acc[mt][nt][half * 2 + 0] + eo0[cb]     + eo1[cb];
                dst[cb + 1] = acc[mt][nt][half * 2 + 1] + eo0[cb + 1] + eo1[cb + 1];
            }
        }
    }
}

// ---------------------------------------------------------------------------
extern "C" void kernel_launch(void* const* d_in, const int* in_sizes, int n_in,
                              void* d_out, int out_size)
{
    const float* x       = (const float*)d_in[0];
    const float* gate_w  = (const float*)d_in[1];
    const float* gate_k  = (const float*)d_in[2];
    const float* up_k    = (const float*)d_in[3];
    const float* down_k  = (const float*)d_in[4];
    const float* sh_gate = (const float*)d_in[5];
    const float* sh_up   = (const float*)d_in[6];
    const float* sh_down = (const float*)d_in[7];
    float* out = (float*)d_out;

    // Launches 1-2: routing phase. Launches 3-6: GEMMs (so the ncu capture
    // window, which previously landed on fill_kernel, lands on a GEMM).
    router_kernel<<<NTOK, 128>>>(x, gate_w);
    scanfill_kernel<<<1, 256>>>();

    gemm_gateup_routed<<<dim3(FF / BN, NTOK / BM, NE), 256>>>(x, gate_k, up_k);
    gemm_down_routed<<<dim3(DIM / BN, NTOK / BM, NE), 256>>>(down_k);
    gemm_gateup_shared<<<dim3(FSH / BN, NTOK / BM), 256>>>(x, sh_gate, sh_up);
    gemm_down_shared<<<dim3(DIM / BN, NTOK / BM), 256>>>(sh_down, out);
}

// round 11
// speedup vs baseline: 1.1168x; 1.1168x over previous
#include <cuda_runtime.h>
#include <math.h>
#include <stdint.h>

// Problem constants
#define NTOK 2048
#define DIM  1024
#define FF   4096
#define FSH  2048
#define NE   8
#define TOPK 2
#define NSLOT (NTOK*TOPK)

// Tiling: BM=128, BN=64, BK=16, double-buffered cp.async (R4 config — best)
#define BM 128
#define BN 64
#define BK 16
#define PA 20
#define PB 72

// ---- scratch ----
__device__ float g_act[(size_t)NSLOT * FF];
__device__ float g_eo[(size_t)NSLOT * DIM];
__device__ float g_hs[(size_t)NTOK * FSH];
__device__ float g_sd[(size_t)NTOK * DIM];
__device__ float g_topw[NTOK * TOPK];
__device__ int   g_topi[NTOK * TOPK];
__device__ int   g_slot_tok[NSLOT];
__device__ float g_slot_w[NSLOT];
__device__ int   g_slot_dst[NSLOT];
__device__ int   g_cnt[NE];
__device__ int   g_off[NE + 1];

// ---------------------------------------------------------------------------
__device__ __forceinline__ uint32_t f2tf32(float x) {
    uint32_t r;
    asm("cvt.rna.tf32.f32 %0, %1;" : "=r"(r) : "f"(x));
    return r;
}

__device__ __forceinline__ void mma_tf32(float& c0, float& c1, float& c2, float& c3,
                                         uint32_t a0, uint32_t a1, uint32_t a2, uint32_t a3,
                                         uint32_t b0, uint32_t b1)
{
    asm volatile(
        "mma.sync.aligned.m16n8k8.row.col.f32.tf32.tf32.f32 "
        "{%0,%1,%2,%3},{%4,%5,%6,%7},{%8,%9},{%0,%1,%2,%3};"
        : "+f"(c0), "+f"(c1), "+f"(c2), "+f"(c3)
        : "r"(a0), "r"(a1), "r"(a2), "r"(a3), "r"(b0), "r"(b1));
}

__device__ __forceinline__ void cp16(uint32_t dst_smem, const float* src) {
    asm volatile("cp.async.cg.shared.global [%0], [%1], 16;"
                 :: "r"(dst_smem), "l"(src));
}
#define CP_COMMIT() asm volatile("cp.async.commit_group;")
#define CP_WAIT1()  asm volatile("cp.async.wait_group 1;" ::: "memory")

// ---------------------------------------------------------------------------
// Router: logits + softmax + top-2 per token.
// ---------------------------------------------------------------------------
__global__ void router_kernel(const float* __restrict__ x,
                              const float* __restrict__ gate_w)
{
    const int n = blockIdx.x;
    const int tid = threadIdx.x;
    __shared__ float sred[NE][128];

    float acc[NE];
#pragma unroll
    for (int e = 0; e < NE; e++) acc[e] = 0.f;

    const float* xr = x + (size_t)n * DIM;
    for (int d = tid; d < DIM; d += 128) {
        float xv = xr[d];
#pragma unroll
        for (int e = 0; e < NE; e++)
            acc[e] = fmaf(xv, gate_w[e * DIM + d], acc[e]);
    }
#pragma unroll
    for (int e = 0; e < NE; e++) sred[e][tid] = acc[e];
    __syncthreads();

    if (tid < NE) {
        float s = 0.f;
        for (int i = 0; i < 128; i++) s += sred[tid][i];
        sred[tid][0] = s;
    }
    __syncthreads();

    if (tid == 0) {
        float lg[NE];
#pragma unroll
        for (int e = 0; e < NE; e++) lg[e] = sred[e][0];
        float mx = lg[0];
#pragma unroll
        for (int e = 1; e < NE; e++) mx = fmaxf(mx, lg[e]);
        float se = 0.f, p[NE];
#pragma unroll
        for (int e = 0; e < NE; e++) { p[e] = expf(lg[e] - mx); se += p[e]; }
        float inv = 1.f / se;
#pragma unroll
        for (int e = 0; e < NE; e++) p[e] *= inv;

        int i1 = 0; float v1 = p[0];
#pragma unroll
        for (int e = 1; e < NE; e++) if (p[e] > v1) { v1 = p[e]; i1 = e; }
        int i2 = -1; float v2 = -1.f;
#pragma unroll
        for (int e = 0; e < NE; e++) if (e != i1 && p[e] > v2) { v2 = p[e]; i2 = e; }

        g_topi[n * 2 + 0] = i1;  g_topw[n * 2 + 0] = v1;
        g_topi[n * 2 + 1] = i2;  g_topw[n * 2 + 1] = v2;
    }
}

// ---------------------------------------------------------------------------
// Scan+fill (single block): count, scan, compact.
// ---------------------------------------------------------------------------
__global__ void scanfill_kernel()
{
    __shared__ int sm_cnt[NE];
    __shared__ int sm_off[NE];
    __shared__ int sm_cur[NE];
    const int t = threadIdx.x;

    if (t < NE) sm_cnt[t] = 0;
    __syncthreads();

    for (int i = t; i < NSLOT; i += 256)
        atomicAdd(&sm_cnt[g_topi[i]], 1);
    __syncthreads();

    if (t == 0) {
        int r = 0;
        for (int e = 0; e < NE; e++) {
            sm_off[e] = r;
            sm_cur[e] = 0;
            r += sm_cnt[e];
        }
        g_off[NE] = r;
    }
    __syncthreads();
    if (t < NE) {
        g_cnt[t] = sm_cnt[t];
        g_off[t] = sm_off[t];
    }
    __syncthreads();

    for (int i = t; i < NSLOT; i += 256) {
        int e = g_topi[i];
        int pos = atomicAdd(&sm_cur[e], 1);
        int slot = sm_off[e] + pos;
        g_slot_tok[slot] = i >> 1;
        g_slot_w[slot]   = g_topw[i];
        g_slot_dst[slot] = i;
    }
}

// ---------------------------------------------------------------------------
// MERGED gate+up GEMM + SwiGLU: z in [0,8].  z<8: routed expert z; z==8: shared.
// grid: (FF/BN=64, NTOK/BM=16, 9).  Shared slice uses x-tiles [0, FSH/BN).
// ---------------------------------------------------------------------------
__global__ __launch_bounds__(256)
void gemm_gateup_merged(const float* __restrict__ x,
                        const float* __restrict__ gate_k,
                        const float* __restrict__ up_k,
                        const float* __restrict__ sh_gate,
                        const float* __restrict__ sh_up)
{
    const int z = blockIdx.z;
    const int routed = (z < NE);
    const int n0 = blockIdx.x * BN;
    if (!routed && n0 >= FSH) return;
    const int cnt = routed ? g_cnt[z] : NTOK;
    const int rowbase = blockIdx.y * BM;
    if (rowbase >= cnt) return;
    const int off = routed ? g_off[z] : 0;

    const size_t bpitch = routed ? FF : FSH;
    const float* __restrict__ Bg = routed ? (gate_k + (size_t)z * DIM * FF) : sh_gate;
    const float* __restrict__ Bu = routed ? (up_k   + (size_t)z * DIM * FF) : sh_up;

    __shared__ float Am[2][BM * PA];
    __shared__ float Bgs[2][BK * PB];
    __shared__ float Bus[2][BK * PB];

    const int t = threadIdx.x;
    const int wid = t >> 5, lane = t & 31;
    const int q = lane >> 2, r = lane & 3;
    const int wm = (wid >> 1) * 32;
    const int wn = (wid & 1) * 32;

    const int a_row = t >> 1, a_seg = (t & 1) * 8;
    int m_g = rowbase + a_row;
    if (m_g >= cnt) m_g = cnt - 1;
    const int tok = routed ? g_slot_tok[off + m_g] : m_g;
    const float* a_src = x + (size_t)tok * DIM + a_seg;

    const int b_row = t >> 4, b_col = (t & 15) * 4;
    const float* bg_src = Bg + (size_t)b_row * bpitch + n0 + b_col;
    const float* bu_src = Bu + (size_t)b_row * bpitch + n0 + b_col;

    const uint32_t sAm = (uint32_t)__cvta_generic_to_shared(&Am[0][0]);
    const uint32_t sBg = (uint32_t)__cvta_generic_to_shared(&Bgs[0][0]);
    const uint32_t sBu = (uint32_t)__cvta_generic_to_shared(&Bus[0][0]);
    const uint32_t aoff = (a_row * PA + a_seg) * 4;
    const uint32_t boff = (b_row * PB + b_col) * 4;
    const uint32_t szA = BM * PA * 4, szB = BK * PB * 4;

    float accg[2][4][4], accu[2][4][4];
#pragma unroll
    for (int i = 0; i < 2; i++)
#pragma unroll
        for (int j = 0; j < 4; j++)
#pragma unroll
            for (int c = 0; c < 4; c++) { accg[i][j][c] = 0.f; accu[i][j][c] = 0.f; }

    cp16(sAm + aoff,      a_src);
    cp16(sAm + aoff + 16, a_src + 4);
    cp16(sBg + boff, bg_src);
    cp16(sBu + boff, bu_src);
    CP_COMMIT();

#pragma unroll 1
    for (int k0 = 0; k0 < DIM; k0 += BK) {
        const int cur = (k0 >> 4) & 1;
        if (k0 + BK < DIM) {
            const uint32_t nb = (cur ^ 1);
            cp16(sAm + nb * szA + aoff,      a_src + k0 + BK);
            cp16(sAm + nb * szA + aoff + 16, a_src + k0 + BK + 4);
            cp16(sBg + nb * szB + boff, bg_src + (size_t)(k0 + BK) * bpitch);
            cp16(sBu + nb * szB + boff, bu_src + (size_t)(k0 + BK) * bpitch);
        }
        CP_COMMIT();
        CP_WAIT1();
        __syncthreads();

        const float* A_  = Am[cur];
        const float* BG_ = Bgs[cur];
        const float* BU_ = Bus[cur];
#pragma unroll
        for (int ks = 0; ks < 2; ks++) {
            const int kb = ks * 8;
            uint32_t af[2][4];
#pragma unroll
            for (int mt = 0; mt < 2; mt++) {
                int mr = wm + mt * 16 + q;
                af[mt][0] = f2tf32(A_[mr * PA + kb + r]);
                af[mt][1] = f2tf32(A_[(mr + 8) * PA + kb + r]);
                af[mt][2] = f2tf32(A_[mr * PA + kb + 4 + r]);
                af[mt][3] = f2tf32(A_[(mr + 8) * PA + kb + 4 + r]);
            }
            uint32_t bgf[4][2], buf[4][2];
#pragma unroll
            for (int nt = 0; nt < 4; nt++) {
                int nc = wn + nt * 8 + q;
                bgf[nt][0] = f2tf32(BG_[(kb + r) * PB + nc]);
                bgf[nt][1] = f2tf32(BG_[(kb + 4 + r) * PB + nc]);
                buf[nt][0] = f2tf32(BU_[(kb + r) * PB + nc]);
                buf[nt][1] = f2tf32(BU_[(kb + 4 + r) * PB + nc]);
            }
#pragma unroll
            for (int mt = 0; mt < 2; mt++)
#pragma unroll
                for (int nt = 0; nt < 4; nt++) {
                    mma_tf32(accg[mt][nt][0], accg[mt][nt][1], accg[mt][nt][2], accg[mt][nt][3],
                             af[mt][0], af[mt][1], af[mt][2], af[mt][3], bgf[nt][0], bgf[nt][1]);
                    mma_tf32(accu[mt][nt][0], accu[mt][nt][1], accu[mt][nt][2], accu[mt][nt][3],
                             af[mt][0], af[mt][1], af[mt][2], af[mt][3], buf[nt][0], buf[nt][1]);
                }
        }
        __syncthreads();
    }

#pragma unroll
    for (int mt = 0; mt < 2; mt++) {
        int r0 = wm + mt * 16 + q;
#pragma unroll
        for (int half = 0; half < 2; half++) {
            int m = rowbase + r0 + half * 8;
            if (m < cnt) {
                float w;
                float* dst;
                if (routed) {
                    int slot = off + m;
                    w = g_slot_w[slot];
                    dst = g_act + (size_t)slot * FF + n0;
                } else {
                    w = 1.f;
                    dst = g_hs + (size_t)m * FSH + n0;
                }
#pragma unroll
                for (int nt = 0; nt < 4; nt++) {
                    int cb = wn + nt * 8 + 2 * r;
                    float gv0 = accg[mt][nt][half * 2 + 0];
                    float gv1 = accg[mt][nt][half * 2 + 1];
                    float uv0 = accu[mt][nt][half * 2 + 0];
                    float uv1 = accu[mt][nt][half * 2 + 1];
                    dst[cb]     = w * (gv0 / (1.f + expf(-gv0))) * uv0;
                    dst[cb + 1] = w * (gv1 / (1.f + expf(-gv1))) * uv1;
                }
            }
        }
    }
}

// ---------------------------------------------------------------------------
// MERGED down GEMM: z in [0,8].  z<8: routed (A=g_act, K=FF, scatter to g_eo);
// z==8: shared (A=g_hs, K=FSH, write g_sd).  grid: (DIM/BN=16, NTOK/BM=16, 9)
// ---------------------------------------------------------------------------
__global__ __launch_bounds__(256)
void gemm_down_merged(const float* __restrict__ down_k,
                      const float* __restrict__ sh_down)
{
    const int z = blockIdx.z;
    const int routed = (z < NE);
    const int cnt = routed ? g_cnt[z] : NTOK;
    const int rowbase = blockIdx.y * BM;
    if (rowbase >= cnt) return;
    const int off = routed ? g_off[z] : 0;
    const int n0 = blockIdx.x * BN;
    const int kd = routed ? FF : FSH;
    const float* __restrict__ B = routed ? (down_k + (size_t)z * FF * DIM) : sh_down;

    __shared__ float Am[2][BM * PA];
    __shared__ float Bs[2][BK * PB];

    const int t = threadIdx.x;
    const int wid = t >> 5, lane = t & 31;
    const int q = lane >> 2, r = lane & 3;
    const int wm = (wid >> 1) * 32;
    const int wn = (wid & 1) * 32;

    const int a_row = t >> 1, a_seg = (t & 1) * 8;
    int m_g = rowbase + a_row;
    if (m_g >= cnt) m_g = cnt - 1;
    const float* a_src = routed
        ? (g_act + (size_t)(off + m_g) * FF + a_seg)
        : (g_hs + (size_t)m_g * FSH + a_seg);

    const int b_row = t >> 4, b_col = (t & 15) * 4;
    const float* b_src = B + (size_t)b_row * DIM + n0 + b_col;

    const uint32_t sAm = (uint32_t)__cvta_generic_to_shared(&Am[0][0]);
    const uint32_t sBs = (uint32_t)__cvta_generic_to_shared(&Bs[0][0]);
    const uint32_t aoff = (a_row * PA + a_seg) * 4;
    const uint32_t boff = (b_row * PB + b_col) * 4;
    const uint32_t szA = BM * PA * 4, szB = BK * PB * 4;

    float acc[2][4][4];
#pragma unroll
    for (int i = 0; i < 2; i++)
#pragma unroll
        for (int j = 0; j < 4; j++)
#pragma unroll
            for (int c = 0; c < 4; c++) acc[i][j][c] = 0.f;

    cp16(sAm + aoff,      a_src);
    cp16(sAm + aoff + 16, a_src + 4);
    cp16(sBs + boff, b_src);
    CP_COMMIT();

#pragma unroll 1
    for (int k0 = 0; k0 < kd; k0 += BK) {
        const int cur = (k0 >> 4) & 1;
        if (k0 + BK < kd) {
            const uint32_t nb = (cur ^ 1);
            cp16(sAm + nb * szA + aoff,      a_src + k0 + BK);
            cp16(sAm + nb * szA + aoff + 16, a_src + k0 + BK + 4);
            cp16(sBs + nb * szB + boff, b_src + (size_t)(k0 + BK) * DIM);
        }
        CP_COMMIT();
        CP_WAIT1();
        __syncthreads();

        const float* A_ = Am[cur];
        const float* B_ = Bs[cur];
#pragma unroll
        for (int ks = 0; ks < 2; ks++) {
            const int kb = ks * 8;
            uint32_t af[2][4];
#pragma unroll
            for (int mt = 0; mt < 2; mt++) {
                int mr = wm + mt * 16 + q;
                af[mt][0] = f2tf32(A_[mr * PA + kb + r]);
                af[mt][1] = f2tf32(A_[(mr + 8) * PA + kb + r]);
                af[mt][2] = f2tf32(A_[mr * PA + kb + 4 + r]);
                af[mt][3] = f2tf32(A_[(mr + 8) * PA + kb + 4 + r]);
            }
            uint32_t bf[4][2];
#pragma unroll
            for (int nt = 0; nt < 4; nt++) {
                int nc = wn + nt * 8 + q;
                bf[nt][0] = f2tf32(B_[(kb + r) * PB + nc]);
                bf[nt][1] = f2tf32(B_[(kb + 4 + r) * PB + nc]);
            }
#pragma unroll
            for (int mt = 0; mt < 2; mt++)
#pragma unroll
                for (int nt = 0; nt < 4; nt++)
                    mma_tf32(acc[mt][nt][0], acc[mt][nt][1], acc[mt][nt][2], acc[mt][nt][3],
                             af[mt][0], af[mt][1], af[mt][2], af[mt][3], bf[nt][0], bf[nt][1]);
        }
        __syncthreads();
    }

#pragma unroll
    for (int mt = 0; mt < 2; mt++) {
        int r0 = wm + mt * 16 + q;
#pragma unroll
        for (int half = 0; half < 2; half++) {
            int m = rowbase + r0 + half * 8;
            if (m < cnt) {
                float* dst = routed
                    ? (g_eo + (size_t)g_slot_dst[off + m] * DIM + n0)
                    : (g_sd + (size_t)m * DIM + n0);
#pragma unroll
                for (int nt = 0; nt < 4; nt++) {
                    int cb = wn + nt * 8 + 2 * r;
                    dst[cb]     = acc[mt][nt][half * 2 + 0];
                    dst[cb + 1] = acc[mt][nt][half * 2 + 1];
                }
            }
        }
    }
}

// ---------------------------------------------------------------------------
// Final combine: out[n,:] = (g_sd[n,:] + g_eo[2n,:]) + g_eo[2n+1,:]
// Same addition order as the previous fused epilogue -> bit-identical.
// ---------------------------------------------------------------------------
__global__ void combine_kernel(float* __restrict__ out)
{
    const int gi = blockIdx.x * blockDim.x + threadIdx.x;   // float4 index
    const int n  = gi / (DIM / 4);
    const int dv = gi % (DIM / 4);
    float4 sd = ((const float4*)g_sd)[(size_t)n * (DIM / 4) + dv];
    float4 e0 = ((const float4*)g_eo)[(size_t)(2 * n)     * (DIM / 4) + dv];
    float4 e1 = ((const float4*)g_eo)[(size_t)(2 * n + 1) * (DIM / 4) + dv];
    float4 o;
    o.x = sd.x + e0.x + e1.x;
    o.y = sd.y + e0.y + e1.y;
    o.z = sd.z + e0.z + e1.z;
    o.w = sd.w + e0.w + e1.w;
    ((float4*)out)[(size_t)n * (DIM / 4) + dv] = o;
}

// ---------------------------------------------------------------------------
extern "C" void kernel_launch(void* const* d_in, const int* in_sizes, int n_in,
                              void* d_out, int out_size)
{
    const float* x       = (const float*)d_in[0];
    const float* gate_w  = (const float*)d_in[1];
    const float* gate_k  = (const float*)d_in[2];
    const float* up_k    = (const float*)d_in[3];
    const float* down_k  = (const float*)d_in[4];
    const float* sh_gate = (const float*)d_in[5];
    const float* sh_up   = (const float*)d_in[6];
    const float* sh_down = (const float*)d_in[7];
    float* out = (float*)d_out;

    router_kernel<<<NTOK, 128>>>(x, gate_w);
    scanfill_kernel<<<1, 256>>>();

    // L1: routed + shared gate/up concurrently (z = 0..7 routed, 8 shared)
    gemm_gateup_merged<<<dim3(FF / BN, NTOK / BM, NE + 1), 256>>>(
        x, gate_k, up_k, sh_gate, sh_up);

    // L2: routed down (-> g_eo) + shared down (-> g_sd) concurrently
    gemm_down_merged<<<dim3(DIM / BN, NTOK / BM, NE + 1), 256>>>(down_k, sh_down);

    // L3: final combine
    combine_kernel<<<(NTOK * DIM / 4) / 256, 256>>>(out);
}